// round 3
// baseline (speedup 1.0000x reference)
#include <cuda_runtime.h>
#include <cuda_bf16.h>

#define N_NODES 50000
#define D_IN    128
#define D_H     128
#define D_Z2    64      // concatenated [W_mu | W_ls] output width
#define D_Z     32

// -------- device scratch (no allocations allowed) --------
__device__ __align__(16) float d_deg [N_NODES];
__device__ __align__(16) float d_dinv[N_NODES];
__device__ __align__(16) float d_g1  [N_NODES * D_H];   // h0 * dinv   (gather source, layer 1)
__device__ __align__(16) float d_acc1[N_NODES * D_H];   // aggregation accumulator, layer 1
__device__ __align__(16) float d_h   [N_NODES * D_H];   // relu(acc1 + b1)
__device__ __align__(16) float d_g2  [N_NODES * D_Z2];  // z0 * dinv
__device__ __align__(16) float d_acc2[N_NODES * D_Z2];
__device__ __align__(16) float d_Wcat[D_H * D_Z2];      // [128][64] = [W_mu | W_ls]

// -------- small elementwise kernels --------
__global__ void init_deg_kernel(float* __restrict__ deg, int n) {
    int i = blockIdx.x * blockDim.x + threadIdx.x;
    if (i < n) deg[i] = 1.0f;   // self-loop
}

__global__ void deg_accum_kernel(float* __restrict__ deg, const int* __restrict__ dst, int E) {
    int i = blockIdx.x * blockDim.x + threadIdx.x;
    if (i < E) atomicAdd(&deg[dst[i]], 1.0f);
}

__global__ void dinv_kernel(const float* __restrict__ deg, float* __restrict__ dinv, int n) {
    int i = blockIdx.x * blockDim.x + threadIdx.x;
    if (i < n) dinv[i] = rsqrtf(deg[i]);  // deg >= 1 always
}

__global__ void wcat_kernel(float* __restrict__ Wcat,
                            const float* __restrict__ Wmu, const float* __restrict__ Wls) {
    int i = blockIdx.x * blockDim.x + threadIdx.x;   // over 128*64
    if (i < D_H * D_Z2) {
        int k = i / D_Z2, j = i % D_Z2;
        Wcat[i] = (j < D_Z) ? Wmu[k * D_Z + j] : Wls[k * D_Z + (j - D_Z)];
    }
}

// -------- GEMM with fused epilogue: g = (X@W)*dinv, acc = (X@W)*dinv^2 --------
// Block computes 32 rows x NOUT cols; 256 threads; each thread 4 rows x TN cols.
template <int TN>
__global__ __launch_bounds__(256) void gemm_ep_kernel(
    const float* __restrict__ X, const float* __restrict__ W,
    const float* __restrict__ dinv,
    float* __restrict__ g, float* __restrict__ acc, int nrows)
{
    constexpr int NOUT = 32 * TN;
    constexpr int KT = 16;
    __shared__ float Xs[32][KT];
    __shared__ float Ws[KT][NOUT];

    const int tid = threadIdx.x;
    const int tx = tid & 31;
    const int ty = tid >> 5;          // 0..7
    const int row0 = blockIdx.x * 32;

    float accv[4][TN];
#pragma unroll
    for (int i = 0; i < 4; i++)
#pragma unroll
        for (int c = 0; c < TN; c++) accv[i][c] = 0.0f;

    for (int k0 = 0; k0 < D_IN; k0 += KT) {
        // load X tile: 32 rows x 16 k = 128 float4, threads 0..127
        if (tid < 128) {
            int r  = tid >> 2;
            int c4 = (tid & 3) * 4;
            int gr = row0 + r;
            float4 v = make_float4(0.f, 0.f, 0.f, 0.f);
            if (gr < nrows)
                v = *reinterpret_cast<const float4*>(X + (size_t)gr * D_IN + k0 + c4);
            *reinterpret_cast<float4*>(&Xs[r][c4]) = v;
        }
        // load W tile: KT x NOUT
        {
            constexpr int NV = KT * NOUT / 4;
            for (int i = tid; i < NV; i += 256) {
                int kk = i / (NOUT / 4);
                int c4 = (i % (NOUT / 4)) * 4;
                *reinterpret_cast<float4*>(&Ws[kk][c4]) =
                    *reinterpret_cast<const float4*>(W + (size_t)(k0 + kk) * NOUT + c4);
            }
        }
        __syncthreads();

#pragma unroll
        for (int kk = 0; kk < KT; kk++) {
            float b[TN];
            if constexpr (TN == 4) {
                float4 bv = *reinterpret_cast<const float4*>(&Ws[kk][tx * 4]);
                b[0] = bv.x; b[1] = bv.y; b[2] = bv.z; b[3] = bv.w;
            } else {
                float2 bv = *reinterpret_cast<const float2*>(&Ws[kk][tx * 2]);
                b[0] = bv.x; b[1] = bv.y;
            }
            float a[4];
#pragma unroll
            for (int i = 0; i < 4; i++) a[i] = Xs[ty * 4 + i][kk];
#pragma unroll
            for (int i = 0; i < 4; i++)
#pragma unroll
                for (int c = 0; c < TN; c++)
                    accv[i][c] = fmaf(a[i], b[c], accv[i][c]);
        }
        __syncthreads();
    }

    // epilogue
#pragma unroll
    for (int i = 0; i < 4; i++) {
        int r = row0 + ty * 4 + i;
        if (r < nrows) {
            float di = dinv[r];
            float di2 = di * di;
            size_t base = (size_t)r * NOUT + tx * TN;
            if constexpr (TN == 4) {
                float4 gv = make_float4(accv[i][0] * di, accv[i][1] * di,
                                        accv[i][2] * di, accv[i][3] * di);
                float4 av = make_float4(accv[i][0] * di2, accv[i][1] * di2,
                                        accv[i][2] * di2, accv[i][3] * di2);
                *reinterpret_cast<float4*>(g + base)   = gv;
                *reinterpret_cast<float4*>(acc + base) = av;
            } else {
                float2 gv = make_float2(accv[i][0] * di, accv[i][1] * di);
                float2 av = make_float2(accv[i][0] * di2, accv[i][1] * di2);
                *reinterpret_cast<float2*>(g + base)   = gv;
                *reinterpret_cast<float2*>(acc + base) = av;
            }
        }
    }
}

// -------- edge aggregation: acc[dst] += g[src] * dinv[dst], warp per edge --------
template <int F>
__global__ __launch_bounds__(256) void agg_kernel(
    const int* __restrict__ src, const int* __restrict__ dst, int E,
    const float* __restrict__ dinv, const float* __restrict__ g,
    float* __restrict__ acc)
{
    int warp = (blockIdx.x * blockDim.x + threadIdx.x) >> 5;
    int lane = threadIdx.x & 31;
    if (warp >= E) return;
    int s = src[warp];
    int d = dst[warp];
    float w = dinv[d];
    constexpr int V = F / 32;   // 4 (F=128) or 2 (F=64)
    const float* gp = g + (size_t)s * F + lane * V;
    float* ap = acc + (size_t)d * F + lane * V;
    if constexpr (V == 4) {
        float4 v = *reinterpret_cast<const float4*>(gp);
        atomicAdd(ap + 0, v.x * w);
        atomicAdd(ap + 1, v.y * w);
        atomicAdd(ap + 2, v.z * w);
        atomicAdd(ap + 3, v.w * w);
    } else {
        float2 v = *reinterpret_cast<const float2*>(gp);
        atomicAdd(ap + 0, v.x * w);
        atomicAdd(ap + 1, v.y * w);
    }
}

// -------- relu(acc1 + b1) -> h --------
__global__ void relu_bias_kernel(const float* __restrict__ acc1, float* __restrict__ h,
                                 const float* __restrict__ b1, int n) {
    int i = blockIdx.x * blockDim.x + threadIdx.x;
    if (i < n * D_H) {
        int f = i & (D_H - 1);
        h[i] = fmaxf(acc1[i] + b1[f], 0.0f);
    }
}

// -------- split acc2 into (z_mu | z_logstd) with biases --------
__global__ void out_kernel(const float* __restrict__ acc2,
                           const float* __restrict__ bmu, const float* __restrict__ bls,
                           float* __restrict__ out, int n) {
    int i = blockIdx.x * blockDim.x + threadIdx.x;
    if (i < n * D_Z) {
        int r = i / D_Z, j = i % D_Z;
        out[i]                   = acc2[(size_t)r * D_Z2 + j]       + bmu[j];
        out[(size_t)n * D_Z + i] = acc2[(size_t)r * D_Z2 + D_Z + j] + bls[j];
    }
}

extern "C" void kernel_launch(void* const* d_in, const int* in_sizes, int n_in,
                              void* d_out, int out_size)
{
    const float* x    = (const float*)d_in[0];
    const int*   ei1  = (const int*)d_in[1];   // JAX default: int64 request downgrades to int32
    const int*   ei2  = (const int*)d_in[2];
    const float* W1   = (const float*)d_in[3];
    const float* b1   = (const float*)d_in[4];
    const float* Wmu  = (const float*)d_in[5];
    const float* bmu  = (const float*)d_in[6];
    const float* Wls  = (const float*)d_in[7];
    const float* bls  = (const float*)d_in[8];
    float* out = (float*)d_out;

    // Resolve true device addresses of __device__ globals (host shadow symbols
    // are NOT device pointers; passing them silently hits host memory via ATS).
    float *p_deg, *p_dinv, *p_g1, *p_acc1, *p_h, *p_g2, *p_acc2, *p_Wcat;
    cudaGetSymbolAddress((void**)&p_deg,  d_deg);
    cudaGetSymbolAddress((void**)&p_dinv, d_dinv);
    cudaGetSymbolAddress((void**)&p_g1,   d_g1);
    cudaGetSymbolAddress((void**)&p_acc1, d_acc1);
    cudaGetSymbolAddress((void**)&p_h,    d_h);
    cudaGetSymbolAddress((void**)&p_g2,   d_g2);
    cudaGetSymbolAddress((void**)&p_acc2, d_acc2);
    cudaGetSymbolAddress((void**)&p_Wcat, d_Wcat);

    const int n  = in_sizes[0] / D_IN;     // 50000
    const int E1 = in_sizes[1] / 2;        // 600000
    const int E2 = in_sizes[2] / 2;        // 200000
    const int* src1 = ei1;
    const int* dst1 = ei1 + E1;
    const int* src2 = ei2;
    const int* dst2 = ei2 + E2;

    const int T = 256;
    // 1) degrees (self-loop = init 1)
    init_deg_kernel<<<(n + T - 1) / T, T>>>(p_deg, n);
    deg_accum_kernel<<<(E1 + T - 1) / T, T>>>(p_deg, dst1, E1);
    deg_accum_kernel<<<(E2 + T - 1) / T, T>>>(p_deg, dst2, E2);
    dinv_kernel<<<(n + T - 1) / T, T>>>(p_deg, p_dinv, n);

    // 2) concat weight for layer 2
    wcat_kernel<<<(D_H * D_Z2 + T - 1) / T, T>>>(p_Wcat, Wmu, Wls);

    // 3) layer 1: h0 = x@W1 ; g1 = h0*dinv ; acc1 = h0*dinv^2 (self-loop)
    int gemm_blocks = (n + 31) / 32;
    gemm_ep_kernel<4><<<gemm_blocks, 256>>>(x, W1, p_dinv, p_g1, p_acc1, n);

    // 4) edge scatter, 128-wide (warp per edge -> 8 edges per block)
    agg_kernel<128><<<(E1 + 7) / 8, 256>>>(src1, dst1, E1, p_dinv, p_g1, p_acc1);
    agg_kernel<128><<<(E2 + 7) / 8, 256>>>(src2, dst2, E2, p_dinv, p_g1, p_acc1);

    // 5) h = relu(acc1 + b1)
    relu_bias_kernel<<<(n * D_H + T - 1) / T, T>>>(p_acc1, p_h, b1, n);

    // 6) layer 2 (mu and logstd fused): z0 = h@Wcat ; g2/acc2
    gemm_ep_kernel<2><<<gemm_blocks, 256>>>(p_h, p_Wcat, p_dinv, p_g2, p_acc2, n);

    // 7) edge scatter, 64-wide
    agg_kernel<64><<<(E1 + 7) / 8, 256>>>(src1, dst1, E1, p_dinv, p_g2, p_acc2);
    agg_kernel<64><<<(E2 + 7) / 8, 256>>>(src2, dst2, E2, p_dinv, p_g2, p_acc2);

    // 8) outputs
    out_kernel<<<(n * D_Z + T - 1) / T, T>>>(p_acc2, bmu, bls, out, n);
}

// round 4
// speedup vs baseline: 1.8249x; 1.8249x over previous
#include <cuda_runtime.h>
#include <cuda_bf16.h>

#define N_NODES 50000
#define D_IN    128
#define D_H     128
#define D_Z2    64
#define D_Z     32
#define MAX_E   800000

// -------- device scratch --------
__device__ __align__(16) float d_dinv[N_NODES];
__device__ __align__(16) int   d_cnt [N_NODES];
__device__ __align__(16) int   d_cur [N_NODES];
__device__ __align__(16) int   d_rs  [N_NODES + 1];
__device__ __align__(16) int   d_csr [MAX_E];
__device__ __align__(16) float d_g1  [N_NODES * D_H];   // (x@W1)*dinv
__device__ __align__(16) float d_h   [N_NODES * D_H];   // layer-1 output
__device__ __align__(16) float d_g2  [N_NODES * D_Z2];  // (h@Wcat)*dinv
__device__ __align__(16) float d_Wcat[D_H * D_Z2];

// -------- CSR build --------
__global__ void zero_int_kernel(int* __restrict__ a, int n) {
    int i = blockIdx.x * blockDim.x + threadIdx.x;
    if (i < n) a[i] = 0;
}

__global__ void hist_kernel(int* __restrict__ cnt, const int* __restrict__ dst, int E) {
    int i = blockIdx.x * blockDim.x + threadIdx.x;
    if (i < E) atomicAdd(&cnt[dst[i]], 1);
}

// single-block exclusive scan of cnt[0..n) -> rs, rs[n] = total; also dinv
__global__ void scan_kernel(const int* __restrict__ cnt, int* __restrict__ rs,
                            float* __restrict__ dinv, int n) {
    const int T = 1024;
    __shared__ int sums[T];
    int t = threadIdx.x;
    int C = (n + T - 1) / T;
    int lo = t * C, hi = min(lo + C, n);
    int s = 0;
    for (int i = lo; i < hi; i++) s += cnt[i];
    sums[t] = s;
    __syncthreads();
    // inclusive Hillis-Steele
    for (int off = 1; off < T; off <<= 1) {
        int tmp = (t >= off) ? sums[t - off] : 0;
        __syncthreads();
        sums[t] += tmp;
        __syncthreads();
    }
    int run = sums[t] - s;   // exclusive prefix for this thread's chunk
    for (int i = lo; i < hi; i++) {
        rs[i] = run;
        dinv[i] = rsqrtf((float)(cnt[i] + 1));  // +1 self loop
        run += cnt[i];
    }
    if (t == T - 1) rs[n] = sums[T - 1];
}

__global__ void scatter_kernel(const int* __restrict__ src, const int* __restrict__ dst, int E,
                               const int* __restrict__ rs, int* __restrict__ cur,
                               int* __restrict__ csr) {
    int i = blockIdx.x * blockDim.x + threadIdx.x;
    if (i < E) {
        int d = dst[i];
        int pos = atomicAdd(&cur[d], 1);
        csr[rs[d] + pos] = src[i];
    }
}

__global__ void wcat_kernel(float* __restrict__ Wcat,
                            const float* __restrict__ Wmu, const float* __restrict__ Wls) {
    int i = blockIdx.x * blockDim.x + threadIdx.x;
    if (i < D_H * D_Z2) {
        int k = i / D_Z2, j = i % D_Z2;
        Wcat[i] = (j < D_Z) ? Wmu[k * D_Z + j] : Wls[k * D_Z + (j - D_Z)];
    }
}

// -------- GEMM with epilogue: g = (X@W)*dinv --------
template <int TN>
__global__ __launch_bounds__(256) void gemm_ep_kernel(
    const float* __restrict__ X, const float* __restrict__ W,
    const float* __restrict__ dinv, float* __restrict__ g, int nrows)
{
    constexpr int NOUT = 32 * TN;
    constexpr int KT = 16;
    __shared__ float Xs[32][KT];
    __shared__ float Ws[KT][NOUT];

    const int tid = threadIdx.x;
    const int tx = tid & 31;
    const int ty = tid >> 5;
    const int row0 = blockIdx.x * 32;

    float accv[4][TN];
#pragma unroll
    for (int i = 0; i < 4; i++)
#pragma unroll
        for (int c = 0; c < TN; c++) accv[i][c] = 0.0f;

    for (int k0 = 0; k0 < D_IN; k0 += KT) {
        if (tid < 128) {
            int r = tid >> 2;
            int c4 = (tid & 3) * 4;
            int gr = row0 + r;
            float4 v = make_float4(0.f, 0.f, 0.f, 0.f);
            if (gr < nrows)
                v = *reinterpret_cast<const float4*>(X + (size_t)gr * D_IN + k0 + c4);
            *reinterpret_cast<float4*>(&Xs[r][c4]) = v;
        }
        {
            constexpr int NV = KT * NOUT / 4;
            for (int i = tid; i < NV; i += 256) {
                int kk = i / (NOUT / 4);
                int c4 = (i % (NOUT / 4)) * 4;
                *reinterpret_cast<float4*>(&Ws[kk][c4]) =
                    *reinterpret_cast<const float4*>(W + (size_t)(k0 + kk) * NOUT + c4);
            }
        }
        __syncthreads();

#pragma unroll
        for (int kk = 0; kk < KT; kk++) {
            float b[TN];
            if constexpr (TN == 4) {
                float4 bv = *reinterpret_cast<const float4*>(&Ws[kk][tx * 4]);
                b[0] = bv.x; b[1] = bv.y; b[2] = bv.z; b[3] = bv.w;
            } else {
                float2 bv = *reinterpret_cast<const float2*>(&Ws[kk][tx * 2]);
                b[0] = bv.x; b[1] = bv.y;
            }
            float a[4];
#pragma unroll
            for (int i = 0; i < 4; i++) a[i] = Xs[ty * 4 + i][kk];
#pragma unroll
            for (int i = 0; i < 4; i++)
#pragma unroll
                for (int c = 0; c < TN; c++)
                    accv[i][c] = fmaf(a[i], b[c], accv[i][c]);
        }
        __syncthreads();
    }

#pragma unroll
    for (int i = 0; i < 4; i++) {
        int r = row0 + ty * 4 + i;
        if (r < nrows) {
            float di = dinv[r];
            size_t base = (size_t)r * NOUT + tx * TN;
            if constexpr (TN == 4) {
                float4 gv = make_float4(accv[i][0] * di, accv[i][1] * di,
                                        accv[i][2] * di, accv[i][3] * di);
                *reinterpret_cast<float4*>(g + base) = gv;
            } else {
                float2 gv = make_float2(accv[i][0] * di, accv[i][1] * di);
                *reinterpret_cast<float2*>(g + base) = gv;
            }
        }
    }
}

// -------- gather aggregation, layer 1 (F=128), fused bias+relu --------
// warp per node: out[d] = relu( (g[d] + sum_in g[s]) * dinv[d] + b )
__global__ __launch_bounds__(256) void agg1_kernel(
    const int* __restrict__ rs, const int* __restrict__ csr,
    const float* __restrict__ g, const float* __restrict__ dinv,
    const float* __restrict__ b1, float* __restrict__ h, int n)
{
    int d = (blockIdx.x * blockDim.x + threadIdx.x) >> 5;
    int lane = threadIdx.x & 31;
    if (d >= n) return;

    const float4* gv = reinterpret_cast<const float4*>(g);
    int col = lane;                    // float4 column index 0..31
    float4 a0 = gv[(size_t)d * 32 + col];      // self loop term
    float4 a1 = make_float4(0.f, 0.f, 0.f, 0.f);

    int e = rs[d], end = rs[d + 1];
    for (; e + 2 <= end; e += 2) {
        int s0 = __ldg(&csr[e]);
        int s1 = __ldg(&csr[e + 1]);
        float4 v0 = gv[(size_t)s0 * 32 + col];
        float4 v1 = gv[(size_t)s1 * 32 + col];
        a0.x += v0.x; a0.y += v0.y; a0.z += v0.z; a0.w += v0.w;
        a1.x += v1.x; a1.y += v1.y; a1.z += v1.z; a1.w += v1.w;
    }
    if (e < end) {
        int s0 = __ldg(&csr[e]);
        float4 v0 = gv[(size_t)s0 * 32 + col];
        a0.x += v0.x; a0.y += v0.y; a0.z += v0.z; a0.w += v0.w;
    }
    float w = dinv[d];
    float4 bb = reinterpret_cast<const float4*>(b1)[col];
    float4 r;
    r.x = fmaxf(fmaf(a0.x + a1.x, w, bb.x), 0.f);
    r.y = fmaxf(fmaf(a0.y + a1.y, w, bb.y), 0.f);
    r.z = fmaxf(fmaf(a0.z + a1.z, w, bb.z), 0.f);
    r.w = fmaxf(fmaf(a0.w + a1.w, w, bb.w), 0.f);
    reinterpret_cast<float4*>(h)[(size_t)d * 32 + col] = r;
}

// -------- gather aggregation, layer 2 (F=64), fused bias + mu/logstd split --------
__global__ __launch_bounds__(256) void agg2_kernel(
    const int* __restrict__ rs, const int* __restrict__ csr,
    const float* __restrict__ g, const float* __restrict__ dinv,
    const float* __restrict__ bmu, const float* __restrict__ bls,
    float* __restrict__ out, int n)
{
    int d = (blockIdx.x * blockDim.x + threadIdx.x) >> 5;
    int lane = threadIdx.x & 31;
    if (d >= n) return;

    const float2* gv = reinterpret_cast<const float2*>(g);
    int col = lane;                    // float2 column 0..31
    float2 a0 = gv[(size_t)d * 32 + col];
    float2 a1 = make_float2(0.f, 0.f);

    int e = rs[d], end = rs[d + 1];
    for (; e + 2 <= end; e += 2) {
        int s0 = __ldg(&csr[e]);
        int s1 = __ldg(&csr[e + 1]);
        float2 v0 = gv[(size_t)s0 * 32 + col];
        float2 v1 = gv[(size_t)s1 * 32 + col];
        a0.x += v0.x; a0.y += v0.y;
        a1.x += v1.x; a1.y += v1.y;
    }
    if (e < end) {
        int s0 = __ldg(&csr[e]);
        float2 v0 = gv[(size_t)s0 * 32 + col];
        a0.x += v0.x; a0.y += v0.y;
    }
    float w = dinv[d];
    float vx = (a0.x + a1.x) * w;
    float vy = (a0.y + a1.y) * w;
    // cols 0..63: [0,32) = mu, [32,64) = logstd ; lane col covers 2 floats
    int c0 = col * 2, c1 = col * 2 + 1;   // both in same half (c0 even)
    if (c0 < D_Z) {
        float2 o = make_float2(vx + bmu[c0], vy + bmu[c1]);
        reinterpret_cast<float2*>(out)[(size_t)d * 16 + col] = o;
    } else {
        float2 o = make_float2(vx + bls[c0 - D_Z], vy + bls[c1 - D_Z]);
        reinterpret_cast<float2*>(out + (size_t)n * D_Z)[(size_t)d * 16 + (col - 16)] = o;
    }
}

extern "C" void kernel_launch(void* const* d_in, const int* in_sizes, int n_in,
                              void* d_out, int out_size)
{
    const float* x    = (const float*)d_in[0];
    const int*   ei1  = (const int*)d_in[1];
    const int*   ei2  = (const int*)d_in[2];
    const float* W1   = (const float*)d_in[3];
    const float* b1   = (const float*)d_in[4];
    const float* Wmu  = (const float*)d_in[5];
    const float* bmu  = (const float*)d_in[6];
    const float* Wls  = (const float*)d_in[7];
    const float* bls  = (const float*)d_in[8];
    float* out = (float*)d_out;

    float *p_dinv, *p_g1, *p_h, *p_g2, *p_Wcat;
    int *p_cnt, *p_cur, *p_rs, *p_csr;
    cudaGetSymbolAddress((void**)&p_dinv, d_dinv);
    cudaGetSymbolAddress((void**)&p_cnt,  d_cnt);
    cudaGetSymbolAddress((void**)&p_cur,  d_cur);
    cudaGetSymbolAddress((void**)&p_rs,   d_rs);
    cudaGetSymbolAddress((void**)&p_csr,  d_csr);
    cudaGetSymbolAddress((void**)&p_g1,   d_g1);
    cudaGetSymbolAddress((void**)&p_h,    d_h);
    cudaGetSymbolAddress((void**)&p_g2,   d_g2);
    cudaGetSymbolAddress((void**)&p_Wcat, d_Wcat);

    const int n  = in_sizes[0] / D_IN;   // 50000
    const int E1 = in_sizes[1] / 2;      // 600000
    const int E2 = in_sizes[2] / 2;      // 200000
    const int* src1 = ei1; const int* dst1 = ei1 + E1;
    const int* src2 = ei2; const int* dst2 = ei2 + E2;

    const int T = 256;
    // ---- CSR build (shared by both layers) ----
    zero_int_kernel<<<(n + T - 1) / T, T>>>(p_cnt, n);
    zero_int_kernel<<<(n + T - 1) / T, T>>>(p_cur, n);
    hist_kernel<<<(E1 + T - 1) / T, T>>>(p_cnt, dst1, E1);
    hist_kernel<<<(E2 + T - 1) / T, T>>>(p_cnt, dst2, E2);
    scan_kernel<<<1, 1024>>>(p_cnt, p_rs, p_dinv, n);
    scatter_kernel<<<(E1 + T - 1) / T, T>>>(src1, dst1, E1, p_rs, p_cur, p_csr);
    scatter_kernel<<<(E2 + T - 1) / T, T>>>(src2, dst2, E2, p_rs, p_cur, p_csr);

    wcat_kernel<<<(D_H * D_Z2 + T - 1) / T, T>>>(p_Wcat, Wmu, Wls);

    // ---- layer 1 ----
    int gemm_blocks = (n + 31) / 32;
    gemm_ep_kernel<4><<<gemm_blocks, 256>>>(x, W1, p_dinv, p_g1, n);
    agg1_kernel<<<(n * 32 + T - 1) / T, T>>>(p_rs, p_csr, p_g1, p_dinv, b1, p_h, n);

    // ---- layer 2 (fused heads) ----
    gemm_ep_kernel<2><<<gemm_blocks, 256>>>(p_h, p_Wcat, p_dinv, p_g2, n);
    agg2_kernel<<<(n * 32 + T - 1) / T, T>>>(p_rs, p_csr, p_g2, p_dinv, bmu, bls, out, n);
}